// round 7
// baseline (speedup 1.0000x reference)
#include <cuda_runtime.h>

#define SEQ     2048
#define HEADS   8
#define TILE_I  128
#define JG      4
#define NTHREADS (TILE_I * JG)   // 512

__device__ __forceinline__ float ex2f(float x) {
    float y;
    asm("ex2.approx.f32 %0, %1;" : "=f"(y) : "f"(x));
    return y;
}

__global__ __launch_bounds__(NTHREADS)
void su2_attn_kernel(const float* __restrict__ re,
                     const float* __restrict__ im,
                     float* __restrict__ out,
                     int out_size) {
    // Normalized K vectors (4 real dims) and the norm (to reconstruct V).
    __shared__ float4 K4[SEQ];   // 32 KB
    __shared__ float  nrm[SEQ];  // 8 KB

    const int h   = blockIdx.y;
    const int tid = threadIdx.x;

    // Cooperative load + normalize all 2048 keys of this head.
    for (int j = tid; j < SEQ; j += NTHREADS) {
        const int base = j * (HEADS * 2) + h * 2;
        const float2 r = *reinterpret_cast<const float2*>(re + base);
        const float2 m = *reinterpret_cast<const float2*>(im + base);
        const float ss  = r.x * r.x + r.y * r.y + m.x * m.x + m.y * m.y;
        const float rin = rsqrtf(ss);
        K4[j]  = make_float4(r.x * rin, r.y * rin, m.x * rin, m.y * rin);
        nrm[j] = ss * rin;  // = sqrt(ss) = ||spinor||
    }
    __syncthreads();

    const int iq = tid >> 2;     // query within tile: 0..127
    const int jg = tid & 3;      // j-group: 0..3 (adjacent lanes in warp)
    const int i  = blockIdx.x * TILE_I + iq;

    // q scaled by SCALE * log2(e) so the dot feeds ex2 directly.
    const float C = 0.70710678118654752f * 1.44269504088896341f;
    float4 q = K4[i];
    q.x *= C; q.y *= C; q.z *= C; q.w *= C;

    // Logits are bounded in [-1/sqrt(2), 1/sqrt(2)] (unit vectors) ->
    // softmax needs no max subtraction: exp is always safe.
    float l = 0.0f;
    float a0 = 0.0f, a1 = 0.0f, a2 = 0.0f, a3 = 0.0f;

    #pragma unroll 8
    for (int j = jg; j < SEQ; j += JG) {
        const float4 k = K4[j];
        const float s = q.x * k.x + q.y * k.y + q.z * k.z + q.w * k.w;
        const float p = ex2f(s);            // exp(dot * SCALE)
        l += p;
        const float pv = p * nrm[j];        // fold un-normalization of V
        a0 += pv * k.x;   // re d0
        a1 += pv * k.y;   // re d1
        a2 += pv * k.z;   // im d0
        a3 += pv * k.w;   // im d1
    }

    // Combine the 4 j-groups: lanes with same iq differ only in bits 0..1.
    #pragma unroll
    for (int m = 1; m <= 2; m <<= 1) {
        l  += __shfl_xor_sync(0xffffffffu, l,  m);
        a0 += __shfl_xor_sync(0xffffffffu, a0, m);
        a1 += __shfl_xor_sync(0xffffffffu, a1, m);
        a2 += __shfl_xor_sync(0xffffffffu, a2, m);
        a3 += __shfl_xor_sync(0xffffffffu, a3, m);
    }

    if (jg == 0) {
        const float inv = 1.0f / l;
        if (out_size == SEQ * HEADS * 2) {
            // Output = real part only (complex64 coerced to float32 drops imag).
            // float offset = i*16 + h*2 + d
            float2 o = make_float2(a0 * inv, a1 * inv);
            reinterpret_cast<float2*>(out)[i * HEADS + h] = o;
        } else if (out_size == SEQ * HEADS * 4) {
            // Planar: real plane [2048*8*2] then imag plane.
            const int base = i * (HEADS * 2) + h * 2;
            out[base + 0] = a0 * inv;
            out[base + 1] = a1 * inv;
            out[SEQ * HEADS * 2 + base + 0] = a2 * inv;
            out[SEQ * HEADS * 2 + base + 1] = a3 * inv;
        } else {
            // Fallback: complex64 interleaved pairs (re,im) per spinor dim.
            float4 o = make_float4(a0 * inv, a2 * inv, a1 * inv, a3 * inv);
            reinterpret_cast<float4*>(out)[i * HEADS + h] = o;
        }
    }
}

extern "C" void kernel_launch(void* const* d_in, const int* in_sizes, int n_in,
                              void* d_out, int out_size) {
    // dict-insertion order: d_in[0] = spinors_real, d_in[1] = spinors_imag
    const float* re = (const float*)d_in[0];
    const float* im = (const float*)d_in[1];
    float* out = (float*)d_out;

    dim3 grid(SEQ / TILE_I, HEADS);
    su2_attn_kernel<<<grid, NTHREADS>>>(re, im, out, out_size);
}

// round 11
// speedup vs baseline: 1.4217x; 1.4217x over previous
#include <cuda_runtime.h>

#define SEQ     2048
#define HEADS   8
#define TILE_I  128
#define MI      4                 // queries per thread
#define JG      16                // j-groups (lanes) per query slot
#define SLOTS   (TILE_I / MI)     // 32 query slots
#define NTHREADS (SLOTS * JG)     // 512
#define JPAIRS  (SEQ / 2)         // 1024 packed j-pairs

using u64 = unsigned long long;

__device__ __forceinline__ float ex2f(float x) {
    float y;
    asm("ex2.approx.f32 %0, %1;" : "=f"(y) : "f"(x));
    return y;
}
__device__ __forceinline__ u64 pack2(float lo, float hi) {
    u64 r; asm("mov.b64 %0, {%1, %2};" : "=l"(r) : "f"(lo), "f"(hi)); return r;
}
__device__ __forceinline__ void unpack2(u64 v, float& lo, float& hi) {
    asm("mov.b64 {%0, %1}, %2;" : "=f"(lo), "=f"(hi) : "l"(v));
}
__device__ __forceinline__ u64 fma2(u64 a, u64 b, u64 c) {
    u64 d; asm("fma.rn.f32x2 %0, %1, %2, %3;" : "=l"(d) : "l"(a), "l"(b), "l"(c)); return d;
}
__device__ __forceinline__ u64 mul2(u64 a, u64 b) {
    u64 d; asm("mul.rn.f32x2 %0, %1, %2;" : "=l"(d) : "l"(a), "l"(b)); return d;
}
__device__ __forceinline__ u64 add2(u64 a, u64 b) {
    u64 d; asm("add.rn.f32x2 %0, %1, %2;" : "=l"(d) : "l"(a), "l"(b)); return d;
}
__device__ __forceinline__ u64 ex2_2(u64 s) {
    float lo, hi; unpack2(s, lo, hi);
    return pack2(ex2f(lo), ex2f(hi));
}

// SoA, j-pair packed: component c of keys (2jp, 2jp+1) sits in one 8-byte word.
__shared__ float2 s_kx[JPAIRS];
__shared__ float2 s_ky[JPAIRS];
__shared__ float2 s_kz[JPAIRS];
__shared__ float2 s_kw[JPAIRS];
__shared__ float2 s_n [JPAIRS];

__global__ __launch_bounds__(NTHREADS, 1)
void su2_attn_kernel(const float* __restrict__ re,
                     const float* __restrict__ im,
                     float* __restrict__ out) {
    const int h   = blockIdx.y;
    const int tid = threadIdx.x;

    float* kx = reinterpret_cast<float*>(s_kx);
    float* ky = reinterpret_cast<float*>(s_ky);
    float* kz = reinterpret_cast<float*>(s_kz);
    float* kw = reinterpret_cast<float*>(s_kw);
    float* nn = reinterpret_cast<float*>(s_n);

    // Phase 1: normalize all 2048 keys of this head into smem (SoA).
    #pragma unroll
    for (int j = tid; j < SEQ; j += NTHREADS) {
        const int base = j * (HEADS * 2) + h * 2;
        const float2 r = *reinterpret_cast<const float2*>(re + base);
        const float2 m = *reinterpret_cast<const float2*>(im + base);
        const float ss  = r.x * r.x + r.y * r.y + m.x * m.x + m.y * m.y;
        const float rin = rsqrtf(ss);
        kx[j] = r.x * rin;
        ky[j] = r.y * rin;
        kz[j] = m.x * rin;
        kw[j] = m.y * rin;
        nn[j] = ss * rin;            // ||spinor|| (reconstructs unnormalized V)
    }
    __syncthreads();

    const int slot = tid >> 4;       // 0..31
    const int jg   = tid & 15;       // 0..15, adjacent lanes in warp
    const int ibase = blockIdx.x * TILE_I + slot;

    // exp(dot * SCALE) == ex2(dot * SCALE*log2(e))
    const float C = 0.70710678118654752f * 1.44269504088896341f;

    // Broadcast-packed query constants (4 queries per thread).
    u64 qx[MI], qy[MI], qz[MI], qw[MI];
    #pragma unroll
    for (int q = 0; q < MI; q++) {
        const int i = ibase + q * SLOTS;
        float vx = kx[i] * C, vy = ky[i] * C, vz = kz[i] * C, vw = kw[i] * C;
        qx[q] = pack2(vx, vx);
        qy[q] = pack2(vy, vy);
        qz[q] = pack2(vz, vz);
        qw[q] = pack2(vw, vw);
    }

    u64 lacc[MI], a0[MI], a1[MI];
    #pragma unroll
    for (int q = 0; q < MI; q++) { lacc[q] = 0ull; a0[q] = 0ull; a1[q] = 0ull; }

    // Logits bounded in [-1/sqrt2, 1/sqrt2]: no max-subtraction needed.
    #pragma unroll 4
    for (int jp = jg; jp < JPAIRS; jp += JG) {
        const u64 kx01 = *reinterpret_cast<const u64*>(&s_kx[jp]);
        const u64 ky01 = *reinterpret_cast<const u64*>(&s_ky[jp]);
        const u64 kz01 = *reinterpret_cast<const u64*>(&s_kz[jp]);
        const u64 kw01 = *reinterpret_cast<const u64*>(&s_kw[jp]);
        const u64 n01  = *reinterpret_cast<const u64*>(&s_n [jp]);
        #pragma unroll
        for (int q = 0; q < MI; q++) {
            u64 s = mul2(qw[q], kw01);
            s = fma2(qz[q], kz01, s);
            s = fma2(qy[q], ky01, s);
            s = fma2(qx[q], kx01, s);
            const u64 p  = ex2_2(s);
            lacc[q] = add2(lacc[q], p);
            const u64 pv = mul2(p, n01);     // fold V un-normalization
            a0[q] = fma2(pv, kx01, a0[q]);   // out real, spinor dim 0
            a1[q] = fma2(pv, ky01, a1[q]);   // out real, spinor dim 1
        }
    }

    // Collapse pairs -> scalars, then butterfly-reduce the 16 j-group lanes.
    #pragma unroll
    for (int q = 0; q < MI; q++) {
        float llo, lhi, xlo, xhi, ylo, yhi;
        unpack2(lacc[q], llo, lhi);
        unpack2(a0[q],  xlo, xhi);
        unpack2(a1[q],  ylo, yhi);
        float l = llo + lhi, x = xlo + xhi, y = ylo + yhi;
        #pragma unroll
        for (int m = 1; m <= 8; m <<= 1) {
            l += __shfl_xor_sync(0xffffffffu, l, m);
            x += __shfl_xor_sync(0xffffffffu, x, m);
            y += __shfl_xor_sync(0xffffffffu, y, m);
        }
        if (jg == 0) {
            const int i = ibase + q * SLOTS;
            const float inv = 1.0f / l;
            // real-part output, float32 (1,2048,8,2): offset i*16 + h*2 + d
            reinterpret_cast<float2*>(out)[i * HEADS + h] = make_float2(x * inv, y * inv);
        }
    }
}

extern "C" void kernel_launch(void* const* d_in, const int* in_sizes, int n_in,
                              void* d_out, int out_size) {
    const float* re = (const float*)d_in[0];
    const float* im = (const float*)d_in[1];
    float* out = (float*)d_out;

    dim3 grid(SEQ / TILE_I, HEADS);
    su2_attn_kernel<<<grid, NTHREADS>>>(re, im, out);
}

// round 13
// speedup vs baseline: 1.4390x; 1.0122x over previous
#include <cuda_runtime.h>

#define SEQ     2048
#define HEADS   8
#define TILE_I  128
#define MI      2                  // queries per thread
#define SLOTS   (TILE_I / MI)      // 64 query slots
#define JG      16                 // lanes per slot (j-groups)
#define NTHREADS (SLOTS * JG)      // 1024
#define JPAIRS  (SEQ / 2)          // 1024 packed j-pairs

using u64 = unsigned long long;

__device__ __forceinline__ float ex2f(float x) {
    float y;
    asm("ex2.approx.f32 %0, %1;" : "=f"(y) : "f"(x));
    return y;
}
__device__ __forceinline__ u64 pack2(float lo, float hi) {
    u64 r; asm("mov.b64 %0, {%1, %2};" : "=l"(r) : "f"(lo), "f"(hi)); return r;
}
__device__ __forceinline__ void unpack2(u64 v, float& lo, float& hi) {
    asm("mov.b64 {%0, %1}, %2;" : "=f"(lo), "=f"(hi) : "l"(v));
}
__device__ __forceinline__ u64 fma2(u64 a, u64 b, u64 c) {
    u64 d; asm("fma.rn.f32x2 %0, %1, %2, %3;" : "=l"(d) : "l"(a), "l"(b), "l"(c)); return d;
}
__device__ __forceinline__ u64 mul2(u64 a, u64 b) {
    u64 d; asm("mul.rn.f32x2 %0, %1, %2;" : "=l"(d) : "l"(a), "l"(b)); return d;
}
__device__ __forceinline__ u64 add2(u64 a, u64 b) {
    u64 d; asm("add.rn.f32x2 %0, %1, %2;" : "=l"(d) : "l"(a), "l"(b)); return d;
}
__device__ __forceinline__ u64 ex2_2(u64 s) {
    float lo, hi; unpack2(s, lo, hi);
    return pack2(ex2f(lo), ex2f(hi));
}

// SoA, j-pair packed (one 8B word = component of keys 2jp, 2jp+1).
// kx..kw: normalized key 4-vector. v0,v1: RAW real parts (= unnormalized V).
// 6 * 8KB = 49152 B = exactly the 48KB static smem limit.
__shared__ float2 s_kx[JPAIRS];
__shared__ float2 s_ky[JPAIRS];
__shared__ float2 s_kz[JPAIRS];
__shared__ float2 s_kw[JPAIRS];
__shared__ float2 s_v0[JPAIRS];
__shared__ float2 s_v1[JPAIRS];

__global__ __launch_bounds__(NTHREADS, 1)
void su2_attn_kernel(const float* __restrict__ re,
                     const float* __restrict__ im,
                     float* __restrict__ out) {
    const int h   = blockIdx.y;
    const int tid = threadIdx.x;

    float* kx = reinterpret_cast<float*>(s_kx);
    float* ky = reinterpret_cast<float*>(s_ky);
    float* kz = reinterpret_cast<float*>(s_kz);
    float* kw = reinterpret_cast<float*>(s_kw);
    float* v0 = reinterpret_cast<float*>(s_v0);
    float* v1 = reinterpret_cast<float*>(s_v1);

    // Phase 1: normalize all 2048 keys of this head into smem (SoA).
    #pragma unroll
    for (int j = tid; j < SEQ; j += NTHREADS) {
        const int base = j * (HEADS * 2) + h * 2;
        const float2 r = *reinterpret_cast<const float2*>(re + base);
        const float2 m = *reinterpret_cast<const float2*>(im + base);
        const float ss  = r.x * r.x + r.y * r.y + m.x * m.x + m.y * m.y;
        const float rin = rsqrtf(ss);
        kx[j] = r.x * rin;
        ky[j] = r.y * rin;
        kz[j] = m.x * rin;
        kw[j] = m.y * rin;
        v0[j] = r.x;          // raw = unnormalized V (real part, dim 0)
        v1[j] = r.y;          // raw = unnormalized V (real part, dim 1)
    }
    __syncthreads();

    const int slot  = tid >> 4;      // 0..63
    const int jg    = tid & 15;      // 0..15, adjacent lanes in warp
    const int ibase = blockIdx.x * TILE_I + slot;

    // exp(dot * SCALE) == ex2(dot * SCALE*log2(e))
    const float C = 0.70710678118654752f * 1.44269504088896341f;

    // Broadcast-packed query constants (MI=2 queries per thread).
    u64 qx[MI], qy[MI], qz[MI], qw[MI];
    #pragma unroll
    for (int q = 0; q < MI; q++) {
        const int i = ibase + q * SLOTS;
        float vx = kx[i] * C, vy = ky[i] * C, vz = kz[i] * C, vw = kw[i] * C;
        qx[q] = pack2(vx, vx);
        qy[q] = pack2(vy, vy);
        qz[q] = pack2(vz, vz);
        qw[q] = pack2(vw, vw);
    }

    u64 lacc[MI], a0[MI], a1[MI];
    #pragma unroll
    for (int q = 0; q < MI; q++) { lacc[q] = 0ull; a0[q] = 0ull; a1[q] = 0ull; }

    // Logits bounded in [-1/sqrt2, 1/sqrt2] (unit vectors): softmax needs no
    // max subtraction, exp can never overflow.
    #pragma unroll 4
    for (int jp = jg; jp < JPAIRS; jp += JG) {
        const u64 kx01 = *reinterpret_cast<const u64*>(&s_kx[jp]);
        const u64 ky01 = *reinterpret_cast<const u64*>(&s_ky[jp]);
        const u64 kz01 = *reinterpret_cast<const u64*>(&s_kz[jp]);
        const u64 kw01 = *reinterpret_cast<const u64*>(&s_kw[jp]);
        const u64 v001 = *reinterpret_cast<const u64*>(&s_v0[jp]);
        const u64 v101 = *reinterpret_cast<const u64*>(&s_v1[jp]);
        #pragma unroll
        for (int q = 0; q < MI; q++) {
            u64 s = mul2(qw[q], kw01);
            s = fma2(qz[q], kz01, s);
            s = fma2(qy[q], ky01, s);
            s = fma2(qx[q], kx01, s);
            const u64 p = ex2_2(s);          // exp(dot * SCALE), 2 j's
            lacc[q] = add2(lacc[q], p);
            a0[q] = fma2(p, v001, a0[q]);    // out real, spinor dim 0
            a1[q] = fma2(p, v101, a1[q]);    // out real, spinor dim 1
        }
    }

    // Collapse pairs -> scalars, then butterfly-reduce the 16 j-group lanes.
    #pragma unroll
    for (int q = 0; q < MI; q++) {
        float llo, lhi, xlo, xhi, ylo, yhi;
        unpack2(lacc[q], llo, lhi);
        unpack2(a0[q],  xlo, xhi);
        unpack2(a1[q],  ylo, yhi);
        float l = llo + lhi, x = xlo + xhi, y = ylo + yhi;
        #pragma unroll
        for (int m = 1; m <= 8; m <<= 1) {
            l += __shfl_xor_sync(0xffffffffu, l, m);
            x += __shfl_xor_sync(0xffffffffu, x, m);
            y += __shfl_xor_sync(0xffffffffu, y, m);
        }
        if (jg == 0) {
            const int i = ibase + q * SLOTS;
            const float inv = 1.0f / l;
            // real-part-only output, float32 (1,2048,8,2): offset i*16 + h*2 + d
            reinterpret_cast<float2*>(out)[i * HEADS + h] = make_float2(x * inv, y * inv);
        }
    }
}

extern "C" void kernel_launch(void* const* d_in, const int* in_sizes, int n_in,
                              void* d_out, int out_size) {
    const float* re = (const float*)d_in[0];
    const float* im = (const float*)d_in[1];
    float* out = (float*)d_out;

    dim3 grid(SEQ / TILE_I, HEADS);
    su2_attn_kernel<<<grid, NTHREADS>>>(re, im, out);
}